// round 14
// baseline (speedup 1.0000x reference)
#include <cuda_runtime.h>
#include <cuda_fp16.h>
#include <cstdint>

#define Bb 32
#define Vv 5
#define Nn 196
#define Cc 768
#define Hh 768
#define BN_ROWS 6272            // Bb*Nn
#define BVN 31360               // Bb*Vv*Nn
#define NUM_ITERS 3
#define WMAT (Cc*Cc)            // 589824

// ---------------------------------------------------------------------------
// Scratch (device globals; no runtime allocation allowed) — all fp16
// ---------------------------------------------------------------------------
__device__ __half g_P[(size_t)BVN * Cc];        // proj_x
__device__ __half g_XW1[(size_t)BVN * Hh];      // x @ w1[:C]
__device__ __half g_CW1[(size_t)BN_ROWS * Hh];  // c @ w1[C:]
__device__ __half g_xh[(size_t)BVN * Cc];       // x (fp16)
__device__ __half g_ch[(size_t)BN_ROWS * Cc];   // c (fp16)
// 7 transposed [N,K] weight matrices (fp16): views 0..4, w1a=5, w1b=6
__device__ __half g_W[(size_t)7 * WMAT];

// ---------------------------------------------------------------------------
// Helpers
// ---------------------------------------------------------------------------
__device__ __forceinline__ uint32_t su32(const void* p) {
    uint32_t a;
    asm("{ .reg .u64 t; cvta.to.shared.u64 t, %1; cvt.u32.u64 %0, t; }" : "=r"(a) : "l"(p));
    return a;
}
__device__ __forceinline__ void cpa16(uint32_t d, const void* s) {
    asm volatile("cp.async.cg.shared.global [%0], [%1], 16;" :: "r"(d), "l"(s) : "memory");
}
__device__ __forceinline__ void cp_commit() {
    asm volatile("cp.async.commit_group;" ::: "memory");
}
__device__ __forceinline__ void ldsm4(uint32_t& r0, uint32_t& r1, uint32_t& r2, uint32_t& r3,
                                      uint32_t addr) {
    asm volatile("ldmatrix.sync.aligned.m8n8.x4.shared.b16 {%0,%1,%2,%3}, [%4];"
                 : "=r"(r0), "=r"(r1), "=r"(r2), "=r"(r3) : "r"(addr));
}
__device__ __forceinline__ void mma16816(float* d, const uint32_t* a, const uint32_t* b) {
    asm volatile(
        "mma.sync.aligned.m16n8k16.row.col.f32.f16.f16.f32 "
        "{%0,%1,%2,%3}, {%4,%5,%6,%7}, {%8,%9}, {%0,%1,%2,%3};"
        : "+f"(d[0]), "+f"(d[1]), "+f"(d[2]), "+f"(d[3])
        : "r"(a[0]), "r"(a[1]), "r"(a[2]), "r"(a[3]), "r"(b[0]), "r"(b[1]));
}
__device__ __forceinline__ uint32_t tanh2_fast(uint32_t x2) {
    uint32_t y;
    asm("tanh.approx.f16x2 %0, %1;" : "=r"(y) : "r"(x2));
    return y;
}

// ---------------------------------------------------------------------------
// Prep: one launch. Blocks [0, WBLKS): transpose weights to fp16.
// Blocks [WBLKS, WBLKS+XBLKS): x->fp16 + mean over views -> c0 (fp16).
// ---------------------------------------------------------------------------
#define WBLKS 16128   // 7*WMAT/256
#define XBLKS 4704    // BN_ROWS*(Cc/4)/256

__global__ void prep_kernel(const float* __restrict__ x,
                            const float* __restrict__ w_views,
                            const float* __restrict__ w1) {
    if (blockIdx.x < WBLKS) {
        size_t j = (size_t)blockIdx.x * 256 + threadIdx.x;
        int m = (int)(j / WMAT);
        int r = (int)(j % WMAT);
        int n = r / Cc, k = r % Cc;
        float s;
        if (m < 5)       s = w_views[(size_t)m * WMAT + (size_t)k * Cc + n];
        else if (m == 5) s = w1[(size_t)k * Hh + n];
        else             s = w1[(size_t)(Cc + k) * Hh + n];
        g_W[j] = __float2half_rn(s);
    } else {
        int i = (blockIdx.x - WBLKS) * 256 + threadIdx.x;
        int bn = i / (Cc / 4);
        int cq = (i % (Cc / 4)) * 4;
        int b = bn / Nn, n = bn % Nn;
        float4 acc = make_float4(0.f, 0.f, 0.f, 0.f);
#pragma unroll
        for (int v = 0; v < Vv; v++) {
            size_t row = (size_t)((b * Vv + v) * Nn + n);
            const float4 xv = *(const float4*)(x + row * Cc + cq);
            acc.x += xv.x; acc.y += xv.y; acc.z += xv.z; acc.w += xv.w;
            __half2 a = __floats2half2_rn(xv.x, xv.y);
            __half2 bq = __floats2half2_rn(xv.z, xv.w);
            uint2 p;
            p.x = *(uint32_t*)&a;
            p.y = *(uint32_t*)&bq;
            *(uint2*)(g_xh + row * Cc + cq) = p;
        }
        const float s = 1.0f / Vv;
        __half2 a = __floats2half2_rn(acc.x * s, acc.y * s);
        __half2 bq = __floats2half2_rn(acc.z * s, acc.w * s);
        uint2 p;
        p.x = *(uint32_t*)&a;
        p.y = *(uint32_t*)&bq;
        *(uint2*)(g_ch + (size_t)bn * Cc + cq) = p;
    }
}

// ---------------------------------------------------------------------------
// GEMM core config: f32-accum HMMA, 3-stage cp.async, race-free sync->issue.
// ---------------------------------------------------------------------------
#define STAGE_BYTES 32768          // 2 tiles x 16KB (A, B)
#define NSTAGE 3
#define SMEM_TOTAL  (NSTAGE * STAGE_BYTES)
#define OFF_B  16384
#define NCHUNK 12

// ---------------------------------------------------------------------------
// Combined big GEMM: grid (12, 49, 5). v = blockIdx.z selects the per-view
// row gather. bx<6: B=W_v, out=P; bx>=6: B=w1a, out=XW1.
// ---------------------------------------------------------------------------
__global__ __launch_bounds__(256, 2)
void mma_gemm_big(const __half* __restrict__ Aw, const __half* __restrict__ Wall,
                  __half* __restrict__ P, __half* __restrict__ XW1) {
    extern __shared__ char smem[];
    const uint32_t sb = su32(smem);
    const int tid = threadIdx.x;
    const int lane = tid & 31;
    const int wid = tid >> 5;
    const int warpM = wid & 1;
    const int warpN = wid >> 1;
    const int v = blockIdx.z;
    const int bx = blockIdx.x;
    const bool isP = bx < 6;
    const int NBase = (isP ? bx : bx - 6) * 128;
    const int MBase = blockIdx.y * 128;
    const __half* Bw = Wall + (size_t)(isP ? v : 5) * WMAT;
    __half* Cout = isP ? P : XW1;

    const int lr = tid >> 1;
    const int lc = (tid & 1) * 64;
    int bn0 = MBase + lr;
    int b0 = bn0 / Nn, n0 = bn0 - b0 * Nn;
    int gaRow = (b0 * Vv + v) * Nn + n0;
    const char* aRowPtr = (const char*)(Aw + (size_t)gaRow * Cc) + lc;
    const char* bRowPtr = (const char*)(Bw + (size_t)(NBase + lr) * Cc) + lc;
    uint32_t so[4];
#pragma unroll
    for (int j = 0; j < 4; j++)
        so[j] = (uint32_t)(lr * 128 + ((lc + j * 16) ^ ((lr & 7) << 4)));

    auto issue = [&](int chunk, int stg) {
        uint32_t base = sb + stg * STAGE_BYTES;
        const char* pa = aRowPtr + chunk * 128;
        const char* pb = bRowPtr + chunk * 128;
#pragma unroll
        for (int j = 0; j < 4; j++) {
            cpa16(base + so[j], pa + j * 16);
            cpa16(base + OFF_B + so[j], pb + j * 16);
        }
        cp_commit();
    };

    float acc[4][4][4];
#pragma unroll
    for (int mt = 0; mt < 4; mt++)
#pragma unroll
        for (int nt = 0; nt < 4; nt++)
#pragma unroll
            for (int e = 0; e < 4; e++) acc[mt][nt][e] = 0.f;

    const uint32_t swz = (uint32_t)((lane & 7) << 4);
    const uint32_t aRow0 = (uint32_t)(warpM * 64 + (lane & 15));
    const uint32_t nRow0 = (uint32_t)(warpN * 32 + (lane & 15));
    const uint32_t halfSel = (uint32_t)((lane >> 4) << 4);

    issue(0, 0);
    issue(1, 1);
#pragma unroll 1
    for (int i = 0; i < NCHUNK; i++) {
        if (i + 1 < NCHUNK) asm volatile("cp.async.wait_group 1;" ::: "memory");
        else                asm volatile("cp.async.wait_group 0;" ::: "memory");
        __syncthreads();                       // all consumed chunk i-1; chunk i visible
        if (i + 2 < NCHUNK) issue(i + 2, (i + 2) % NSTAGE);   // safe: stage last used by i-1

        uint32_t base = sb + (i % NSTAGE) * STAGE_BYTES;
#pragma unroll
        for (int k16 = 0; k16 < 4; k16++) {
            const uint32_t bc = (uint32_t)(k16 * 32) + halfSel;
            uint32_t ah[4][4], bh[4][2];
#pragma unroll
            for (int mt = 0; mt < 4; mt++) {
                uint32_t ad = base + (aRow0 + mt * 16) * 128 + (bc ^ swz);
                ldsm4(ah[mt][0], ah[mt][1], ah[mt][2], ah[mt][3], ad);
            }
#pragma unroll
            for (int g = 0; g < 2; g++) {
                uint32_t ad = base + OFF_B + (nRow0 + g * 16) * 128 + (bc ^ swz);
                uint32_t r0, r1, r2, r3;
                ldsm4(r0, r1, r2, r3, ad);
                bh[g * 2 + 0][0] = r0; bh[g * 2 + 0][1] = r2;
                bh[g * 2 + 1][0] = r1; bh[g * 2 + 1][1] = r3;
            }
#pragma unroll
            for (int mt = 0; mt < 4; mt++)
#pragma unroll
                for (int nt = 0; nt < 4; nt++)
                    mma16816(acc[mt][nt], ah[mt], bh[nt]);
        }
    }

    // ---- epilogue (fp16 stores, gathered rows) ----
    int grow[8];
#pragma unroll
    for (int mt = 0; mt < 4; mt++) {
#pragma unroll
        for (int h = 0; h < 2; h++) {
            int m = MBase + warpM * 64 + mt * 16 + (lane >> 2) + h * 8;
            int b = m / Nn, n = m - b * Nn;
            grow[mt * 2 + h] = (b * Vv + v) * Nn + n;
        }
    }
    const int ncol0 = NBase + warpN * 32 + (lane & 3) * 2;
#pragma unroll
    for (int mt = 0; mt < 4; mt++)
#pragma unroll
        for (int nt = 0; nt < 4; nt++) {
            __half2 h01 = __floats2half2_rn(acc[mt][nt][0], acc[mt][nt][1]);
            __half2 h23 = __floats2half2_rn(acc[mt][nt][2], acc[mt][nt][3]);
            *(__half2*)(Cout + (size_t)grow[mt * 2 + 0] * Cc + ncol0 + nt * 8) = h01;
            *(__half2*)(Cout + (size_t)grow[mt * 2 + 1] * Cc + ncol0 + nt * 8) = h23;
        }
}

// ---------------------------------------------------------------------------
// Flat GEMM for CW1 = c @ w1b. CTA 128x128, flat rows, 3-stage pipeline.
// ---------------------------------------------------------------------------
__global__ __launch_bounds__(256, 2)
void mma_gemm_flat(const __half* __restrict__ Aw, const __half* __restrict__ Bw,
                   __half* __restrict__ Cout) {
    extern __shared__ char smem[];
    const uint32_t sb = su32(smem);
    const int tid = threadIdx.x;
    const int lane = tid & 31;
    const int wid = tid >> 5;
    const int warpM = wid & 1;
    const int warpN = wid >> 1;
    const int MBase = blockIdx.y * 128;
    const int NBase = blockIdx.x * 128;

    const int lr = tid >> 1;
    const int lc = (tid & 1) * 64;
    const char* aRowPtr = (const char*)(Aw + (size_t)(MBase + lr) * Cc) + lc;
    const char* bRowPtr = (const char*)(Bw + (size_t)(NBase + lr) * Cc) + lc;
    uint32_t so[4];
#pragma unroll
    for (int j = 0; j < 4; j++)
        so[j] = (uint32_t)(lr * 128 + ((lc + j * 16) ^ ((lr & 7) << 4)));

    auto issue = [&](int chunk, int stg) {
        uint32_t base = sb + stg * STAGE_BYTES;
        const char* pa = aRowPtr + chunk * 128;
        const char* pb = bRowPtr + chunk * 128;
#pragma unroll
        for (int j = 0; j < 4; j++) {
            cpa16(base + so[j], pa + j * 16);
            cpa16(base + OFF_B + so[j], pb + j * 16);
        }
        cp_commit();
    };

    float acc[4][4][4];
#pragma unroll
    for (int mt = 0; mt < 4; mt++)
#pragma unroll
        for (int nt = 0; nt < 4; nt++)
#pragma unroll
            for (int e = 0; e < 4; e++) acc[mt][nt][e] = 0.f;

    const uint32_t swz = (uint32_t)((lane & 7) << 4);
    const uint32_t aRow0 = (uint32_t)(warpM * 64 + (lane & 15));
    const uint32_t nRow0 = (uint32_t)(warpN * 32 + (lane & 15));
    const uint32_t halfSel = (uint32_t)((lane >> 4) << 4);

    issue(0, 0);
    issue(1, 1);
#pragma unroll 1
    for (int i = 0; i < NCHUNK; i++) {
        if (i + 1 < NCHUNK) asm volatile("cp.async.wait_group 1;" ::: "memory");
        else                asm volatile("cp.async.wait_group 0;" ::: "memory");
        __syncthreads();
        if (i + 2 < NCHUNK) issue(i + 2, (i + 2) % NSTAGE);

        uint32_t base = sb + (i % NSTAGE) * STAGE_BYTES;
#pragma unroll
        for (int k16 = 0; k16 < 4; k16++) {
            const uint32_t bc = (uint32_t)(k16 * 32) + halfSel;
            uint32_t ah[4][4], bh[4][2];
#pragma unroll
            for (int mt = 0; mt < 4; mt++) {
                uint32_t ad = base + (aRow0 + mt * 16) * 128 + (bc ^ swz);
                ldsm4(ah[mt][0], ah[mt][1], ah[mt][2], ah[mt][3], ad);
            }
#pragma unroll
            for (int g = 0; g < 2; g++) {
                uint32_t ad = base + OFF_B + (nRow0 + g * 16) * 128 + (bc ^ swz);
                uint32_t r0, r1, r2, r3;
                ldsm4(r0, r1, r2, r3, ad);
                bh[g * 2 + 0][0] = r0; bh[g * 2 + 0][1] = r2;
                bh[g * 2 + 1][0] = r1; bh[g * 2 + 1][1] = r3;
            }
#pragma unroll
            for (int mt = 0; mt < 4; mt++)
#pragma unroll
                for (int nt = 0; nt < 4; nt++)
                    mma16816(acc[mt][nt], ah[mt], bh[nt]);
        }
    }

    const int ncol0 = NBase + warpN * 32 + (lane & 3) * 2;
#pragma unroll
    for (int mt = 0; mt < 4; mt++) {
        int m0 = MBase + warpM * 64 + mt * 16 + (lane >> 2);
#pragma unroll
        for (int nt = 0; nt < 4; nt++) {
            __half2 h01 = __floats2half2_rn(acc[mt][nt][0], acc[mt][nt][1]);
            __half2 h23 = __floats2half2_rn(acc[mt][nt][2], acc[mt][nt][3]);
            *(__half2*)(Cout + (size_t)m0 * Cc + ncol0 + nt * 8) = h01;
            *(__half2*)(Cout + (size_t)(m0 + 8) * Cc + ncol0 + nt * 8) = h23;
        }
    }
}

// ---------------------------------------------------------------------------
// Fused score + softmax + update, 16 bn-rows per block (392 blocks, 512 thr).
// smem staging of CW1 rows (contiguous), b1 (half2), w2 (fp32).
// tanh.approx.f16x2 — math identical to round-13 version.
// ---------------------------------------------------------------------------
#define BN_PER_BLK 16
#define SU_THREADS 512
__global__ __launch_bounds__(SU_THREADS)
void score_update_kernel(const __half* __restrict__ XW1, const __half* __restrict__ CW1,
                         const float* __restrict__ b1, const float* __restrict__ w2,
                         const float* __restrict__ b2, const __half* __restrict__ P,
                         float* __restrict__ OutC, float* __restrict__ Rout, int last) {
    const int bn0 = blockIdx.x * BN_PER_BLK;
    const int tid = threadIdx.x;
    const int wid = tid >> 5;          // 0..15
    const int lane = tid & 31;

    __shared__ __half2 s_b1h[Hh / 2];                 // 1.5 KB
    __shared__ float   s_w2[Hh];                      // 3 KB
    __shared__ __half  s_cw[BN_PER_BLK * Hh];         // 24 KB
    __shared__ float   s_a[BN_PER_BLK * Vv];

    // Phase 0: stage b1 (half2), w2 (fp32), 16 contiguous CW1 rows
    for (int j = tid; j < Hh / 2; j += SU_THREADS) {
        float2 bv = *(const float2*)(b1 + 2 * j);
        s_b1h[j] = __floats2half2_rn(bv.x, bv.y);
    }
    for (int j = tid; j < Hh; j += SU_THREADS) s_w2[j] = w2[j];
    {
        const uint4* src = (const uint4*)(CW1 + (size_t)bn0 * Hh);
        uint4* dst = (uint4*)s_cw;
#pragma unroll
        for (int j = 0; j < (BN_PER_BLK * Hh / 8) / SU_THREADS; j++)   // 3 iters
            dst[tid + j * SU_THREADS] = src[tid + j * SU_THREADS];
    }
    __syncthreads();

    const float b2v = b2[0];

    // Phase 1: 80 dots, warp w handles d = w, w+16, ..., w+64
    float dots[5];
#pragma unroll
    for (int q = 0; q < 5; q++) {
        const int d = wid + q * 16;          // 0..79
        const int ln = d / Vv;               // local bn 0..15
        const int v  = d % Vv;
        const int bn = bn0 + ln;
        const int b = bn / Nn, n = bn % Nn;
        const __half* xr = XW1 + (size_t)((b * Vv + v) * Nn + n) * Hh;
        const __half* cw = s_cw + ln * Hh;
        float sum = 0.f;
#pragma unroll
        for (int h0 = lane * 8; h0 < Hh; h0 += 256) {
            uint4 xv = *(const uint4*)(xr + h0);
            uint4 cv = *(const uint4*)(cw + h0);
            const __half2* px = (const __half2*)&xv;
            const __half2* pc = (const __half2*)&cv;
#pragma unroll
            for (int j = 0; j < 4; j++) {
                __half2 arg = __hadd2(__hadd2(px[j], pc[j]), s_b1h[h0 / 2 + j]);
                uint32_t t2 = tanh2_fast(*(uint32_t*)&arg);
                float2 tf = __half22float2(*(__half2*)&t2);
                int h = h0 + 2 * j;
                sum = fmaf(tf.x, s_w2[h], sum);
                sum = fmaf(tf.y, s_w2[h + 1], sum);
            }
        }
#pragma unroll
        for (int off = 16; off; off >>= 1) sum += __shfl_xor_sync(0xFFFFFFFFu, sum, off);
        dots[q] = sum + b2v;
    }
    if (lane == 0) {
#pragma unroll
        for (int q = 0; q < 5; q++) s_a[wid + q * 16] = dots[q];
    }
    __syncthreads();

    // Phase 2: softmax per local bn (threads 0..15)
    if (tid < BN_PER_BLK) {
        float sv[Vv];
        float mx = -1e30f;
#pragma unroll
        for (int v = 0; v < Vv; v++) {
            sv[v] = s_a[tid * Vv + v];
            mx = fmaxf(mx, sv[v]);
        }
        float den = 0.f;
#pragma unroll
        for (int v = 0; v < Vv; v++) { sv[v] = __expf(sv[v] - mx); den += sv[v]; }
        float inv = 1.0f / den;
#pragma unroll
        for (int v = 0; v < Vv; v++) { sv[v] *= inv; s_a[tid * Vv + v] = sv[v]; }
        if (last) {
            float ent = 0.f;
#pragma unroll
            for (int v = 0; v < Vv; v++) ent -= sv[v] * __logf(sv[v] + 1e-8f);
            Rout[bn0 + tid] = 1.0f - ent * (1.0f / 1.6094379124341003f);  // 1/log(5)
        }
    }
    __syncthreads();

    // Phase 3: weighted sum. 16 ln x 192 chan-slots = 3072 slots / 512 thr = 6 its
#pragma unroll
    for (int it = 0; it < 6; it++) {
        const int slot = tid + it * SU_THREADS;
        const int ln = slot / (Cc / 4);
        const int ch = (slot % (Cc / 4)) * 4;
        const int bn = bn0 + ln;
        const int b = bn / Nn, n = bn % Nn;
        float av[Vv];
#pragma unroll
        for (int v = 0; v < Vv; v++) av[v] = s_a[ln * Vv + v];
        float4 acc = make_float4(0.f, 0.f, 0.f, 0.f);
#pragma unroll
        for (int v = 0; v < Vv; v++) {
            uint2 pv = *(const uint2*)(P + ((size_t)((b * Vv + v) * Nn + n)) * Cc + ch);
            float2 p01 = __half22float2(*(__half2*)&pv.x);
            float2 p23 = __half22float2(*(__half2*)&pv.y);
            acc.x += av[v] * p01.x; acc.y += av[v] * p01.y;
            acc.z += av[v] * p23.x; acc.w += av[v] * p23.y;
        }
        if (last) {
            *(float4*)(OutC + (size_t)bn * Cc + ch) = acc;
        } else {
            __half2 a = __floats2half2_rn(acc.x, acc.y);
            __half2 bq = __floats2half2_rn(acc.z, acc.w);
            uint2 p;
            p.x = *(uint32_t*)&a;
            p.y = *(uint32_t*)&bq;
            *(uint2*)(g_ch + (size_t)bn * Cc + ch) = p;
        }
    }
}

// ---------------------------------------------------------------------------
// Launch
// ---------------------------------------------------------------------------
extern "C" void kernel_launch(void* const* d_in, const int* in_sizes, int n_in,
                              void* d_out, int out_size) {
    const float* x       = (const float*)d_in[0];
    const float* w_views = (const float*)d_in[1];
    const float* w1      = (const float*)d_in[2];
    const float* b1      = (const float*)d_in[3];
    const float* w2      = (const float*)d_in[4];
    const float* b2      = (const float*)d_in[5];
    float* out = (float*)d_out;   // c [B,N,C] then r [B,N]

    __half *P, *XW1, *CW1, *xh, *ch, *W;
    cudaGetSymbolAddress((void**)&P,   g_P);
    cudaGetSymbolAddress((void**)&XW1, g_XW1);
    cudaGetSymbolAddress((void**)&CW1, g_CW1);
    cudaGetSymbolAddress((void**)&xh,  g_xh);
    cudaGetSymbolAddress((void**)&ch,  g_ch);
    cudaGetSymbolAddress((void**)&W,   g_W);

    cudaFuncSetAttribute(mma_gemm_big,  cudaFuncAttributeMaxDynamicSharedMemorySize, SMEM_TOTAL);
    cudaFuncSetAttribute(mma_gemm_flat, cudaFuncAttributeMaxDynamicSharedMemorySize, SMEM_TOTAL);

    // conversions: one launch (weights + x/mean)
    prep_kernel<<<WBLKS + XBLKS, 256>>>(x, w_views, w1);

    // P = x @ w_views and XW1 = x @ w1[:C] in one launch
    {
        dim3 grid(12, BN_ROWS / 128, Vv);   // (12, 49, 5)
        mma_gemm_big<<<grid, 256, SMEM_TOTAL>>>(xh, W, P, XW1);
    }
    // iterations
    for (int it = 0; it < NUM_ITERS; it++) {
        dim3 gridc(Hh / 128, BN_ROWS / 128);   // (6, 49)
        mma_gemm_flat<<<gridc, 256, SMEM_TOTAL>>>(ch, W + (size_t)6 * WMAT, CW1);

        int last = (it == NUM_ITERS - 1) ? 1 : 0;
        float* rdst = out + (size_t)BN_ROWS * Cc;
        score_update_kernel<<<BN_ROWS / BN_PER_BLK, SU_THREADS>>>(XW1, CW1, b1, w2, b2, P, out, rdst, last);
    }
    (void)in_sizes; (void)n_in; (void)out_size;
}

// round 15
// speedup vs baseline: 1.0516x; 1.0516x over previous
#include <cuda_runtime.h>
#include <cuda_fp16.h>
#include <cstdint>

#define Bb 32
#define Vv 5
#define Nn 196
#define Cc 768
#define Hh 768
#define BN_ROWS 6272            // Bb*Nn
#define BVN 31360               // Bb*Vv*Nn
#define NUM_ITERS 3
#define WMAT (Cc*Cc)            // 589824

// ---------------------------------------------------------------------------
// Scratch (device globals; no runtime allocation allowed) — all fp16
// ---------------------------------------------------------------------------
__device__ __half g_P[(size_t)BVN * Cc];        // proj_x
__device__ __half g_XW1[(size_t)BVN * Hh];      // x @ w1[:C]
__device__ __half g_CW1[(size_t)BN_ROWS * Hh];  // c @ w1[C:]
__device__ __half g_xh[(size_t)BVN * Cc];       // x (fp16)
__device__ __half g_ch[(size_t)BN_ROWS * Cc];   // c (fp16)
// 7 transposed [N,K] weight matrices (fp16): views 0..4, w1a=5, w1b=6
__device__ __half g_W[(size_t)7 * WMAT];

// ---------------------------------------------------------------------------
// Helpers
// ---------------------------------------------------------------------------
__device__ __forceinline__ uint32_t su32(const void* p) {
    uint32_t a;
    asm("{ .reg .u64 t; cvta.to.shared.u64 t, %1; cvt.u32.u64 %0, t; }" : "=r"(a) : "l"(p));
    return a;
}
__device__ __forceinline__ void cpa16(uint32_t d, const void* s) {
    asm volatile("cp.async.cg.shared.global [%0], [%1], 16;" :: "r"(d), "l"(s) : "memory");
}
__device__ __forceinline__ void cp_commit() {
    asm volatile("cp.async.commit_group;" ::: "memory");
}
__device__ __forceinline__ void ldsm4(uint32_t& r0, uint32_t& r1, uint32_t& r2, uint32_t& r3,
                                      uint32_t addr) {
    asm volatile("ldmatrix.sync.aligned.m8n8.x4.shared.b16 {%0,%1,%2,%3}, [%4];"
                 : "=r"(r0), "=r"(r1), "=r"(r2), "=r"(r3) : "r"(addr));
}
__device__ __forceinline__ void mma16816(float* d, const uint32_t* a, const uint32_t* b) {
    asm volatile(
        "mma.sync.aligned.m16n8k16.row.col.f32.f16.f16.f32 "
        "{%0,%1,%2,%3}, {%4,%5,%6,%7}, {%8,%9}, {%0,%1,%2,%3};"
        : "+f"(d[0]), "+f"(d[1]), "+f"(d[2]), "+f"(d[3])
        : "r"(a[0]), "r"(a[1]), "r"(a[2]), "r"(a[3]), "r"(b[0]), "r"(b[1]));
}
__device__ __forceinline__ uint32_t tanh2_fast(uint32_t x2) {
    uint32_t y;
    asm("tanh.approx.f16x2 %0, %1;" : "=r"(y) : "r"(x2));
    return y;
}

// ---------------------------------------------------------------------------
// Prep: one launch. Blocks [0, WBLKS): transpose weights to fp16.
// Blocks [WBLKS, WBLKS+XBLKS): x->fp16 + mean over views -> c0 (fp16).
// ---------------------------------------------------------------------------
#define WBLKS 16128   // 7*WMAT/256
#define XBLKS 4704    // BN_ROWS*(Cc/4)/256

__global__ void prep_kernel(const float* __restrict__ x,
                            const float* __restrict__ w_views,
                            const float* __restrict__ w1) {
    if (blockIdx.x < WBLKS) {
        size_t j = (size_t)blockIdx.x * 256 + threadIdx.x;
        int m = (int)(j / WMAT);
        int r = (int)(j % WMAT);
        int n = r / Cc, k = r % Cc;
        float s;
        if (m < 5)       s = w_views[(size_t)m * WMAT + (size_t)k * Cc + n];
        else if (m == 5) s = w1[(size_t)k * Hh + n];
        else             s = w1[(size_t)(Cc + k) * Hh + n];
        g_W[j] = __float2half_rn(s);
    } else {
        int i = (blockIdx.x - WBLKS) * 256 + threadIdx.x;
        int bn = i / (Cc / 4);
        int cq = (i % (Cc / 4)) * 4;
        int b = bn / Nn, n = bn % Nn;
        float4 acc = make_float4(0.f, 0.f, 0.f, 0.f);
#pragma unroll
        for (int v = 0; v < Vv; v++) {
            size_t row = (size_t)((b * Vv + v) * Nn + n);
            const float4 xv = *(const float4*)(x + row * Cc + cq);
            acc.x += xv.x; acc.y += xv.y; acc.z += xv.z; acc.w += xv.w;
            __half2 a = __floats2half2_rn(xv.x, xv.y);
            __half2 bq = __floats2half2_rn(xv.z, xv.w);
            uint2 p;
            p.x = *(uint32_t*)&a;
            p.y = *(uint32_t*)&bq;
            *(uint2*)(g_xh + row * Cc + cq) = p;
        }
        const float s = 1.0f / Vv;
        __half2 a = __floats2half2_rn(acc.x * s, acc.y * s);
        __half2 bq = __floats2half2_rn(acc.z * s, acc.w * s);
        uint2 p;
        p.x = *(uint32_t*)&a;
        p.y = *(uint32_t*)&bq;
        *(uint2*)(g_ch + (size_t)bn * Cc + cq) = p;
    }
}

// ---------------------------------------------------------------------------
// GEMM core config: f32-accum HMMA, 3-stage cp.async, race-free sync->issue.
// ---------------------------------------------------------------------------
#define STAGE_BYTES 32768          // 2 tiles x 16KB (A, B)
#define NSTAGE 3
#define SMEM_TOTAL  (NSTAGE * STAGE_BYTES)
#define OFF_B  16384
#define NCHUNK 12

// ---------------------------------------------------------------------------
// Combined big GEMM: grid (12, 49, 5). v = blockIdx.z selects the per-view
// row gather. bx<6: B=W_v, out=P; bx>=6: B=w1a, out=XW1.
// ---------------------------------------------------------------------------
__global__ __launch_bounds__(256, 2)
void mma_gemm_big(const __half* __restrict__ Aw, const __half* __restrict__ Wall,
                  __half* __restrict__ P, __half* __restrict__ XW1) {
    extern __shared__ char smem[];
    const uint32_t sb = su32(smem);
    const int tid = threadIdx.x;
    const int lane = tid & 31;
    const int wid = tid >> 5;
    const int warpM = wid & 1;
    const int warpN = wid >> 1;
    const int v = blockIdx.z;
    const int bx = blockIdx.x;
    const bool isP = bx < 6;
    const int NBase = (isP ? bx : bx - 6) * 128;
    const int MBase = blockIdx.y * 128;
    const __half* Bw = Wall + (size_t)(isP ? v : 5) * WMAT;
    __half* Cout = isP ? P : XW1;

    const int lr = tid >> 1;
    const int lc = (tid & 1) * 64;
    int bn0 = MBase + lr;
    int b0 = bn0 / Nn, n0 = bn0 - b0 * Nn;
    int gaRow = (b0 * Vv + v) * Nn + n0;
    const char* aRowPtr = (const char*)(Aw + (size_t)gaRow * Cc) + lc;
    const char* bRowPtr = (const char*)(Bw + (size_t)(NBase + lr) * Cc) + lc;
    uint32_t so[4];
#pragma unroll
    for (int j = 0; j < 4; j++)
        so[j] = (uint32_t)(lr * 128 + ((lc + j * 16) ^ ((lr & 7) << 4)));

    auto issue = [&](int chunk, int stg) {
        uint32_t base = sb + stg * STAGE_BYTES;
        const char* pa = aRowPtr + chunk * 128;
        const char* pb = bRowPtr + chunk * 128;
#pragma unroll
        for (int j = 0; j < 4; j++) {
            cpa16(base + so[j], pa + j * 16);
            cpa16(base + OFF_B + so[j], pb + j * 16);
        }
        cp_commit();
    };

    float acc[4][4][4];
#pragma unroll
    for (int mt = 0; mt < 4; mt++)
#pragma unroll
        for (int nt = 0; nt < 4; nt++)
#pragma unroll
            for (int e = 0; e < 4; e++) acc[mt][nt][e] = 0.f;

    const uint32_t swz = (uint32_t)((lane & 7) << 4);
    const uint32_t aRow0 = (uint32_t)(warpM * 64 + (lane & 15));
    const uint32_t nRow0 = (uint32_t)(warpN * 32 + (lane & 15));
    const uint32_t halfSel = (uint32_t)((lane >> 4) << 4);

    issue(0, 0);
    issue(1, 1);
#pragma unroll 1
    for (int i = 0; i < NCHUNK; i++) {
        if (i + 1 < NCHUNK) asm volatile("cp.async.wait_group 1;" ::: "memory");
        else                asm volatile("cp.async.wait_group 0;" ::: "memory");
        __syncthreads();                       // all consumed chunk i-1; chunk i visible
        if (i + 2 < NCHUNK) issue(i + 2, (i + 2) % NSTAGE);   // safe: stage last used by i-1

        uint32_t base = sb + (i % NSTAGE) * STAGE_BYTES;
#pragma unroll
        for (int k16 = 0; k16 < 4; k16++) {
            const uint32_t bc = (uint32_t)(k16 * 32) + halfSel;
            uint32_t ah[4][4], bh[4][2];
#pragma unroll
            for (int mt = 0; mt < 4; mt++) {
                uint32_t ad = base + (aRow0 + mt * 16) * 128 + (bc ^ swz);
                ldsm4(ah[mt][0], ah[mt][1], ah[mt][2], ah[mt][3], ad);
            }
#pragma unroll
            for (int g = 0; g < 2; g++) {
                uint32_t ad = base + OFF_B + (nRow0 + g * 16) * 128 + (bc ^ swz);
                uint32_t r0, r1, r2, r3;
                ldsm4(r0, r1, r2, r3, ad);
                bh[g * 2 + 0][0] = r0; bh[g * 2 + 0][1] = r2;
                bh[g * 2 + 1][0] = r1; bh[g * 2 + 1][1] = r3;
            }
#pragma unroll
            for (int mt = 0; mt < 4; mt++)
#pragma unroll
                for (int nt = 0; nt < 4; nt++)
                    mma16816(acc[mt][nt], ah[mt], bh[nt]);
        }
    }

    // ---- epilogue (fp16 stores, gathered rows) ----
    int grow[8];
#pragma unroll
    for (int mt = 0; mt < 4; mt++) {
#pragma unroll
        for (int h = 0; h < 2; h++) {
            int m = MBase + warpM * 64 + mt * 16 + (lane >> 2) + h * 8;
            int b = m / Nn, n = m - b * Nn;
            grow[mt * 2 + h] = (b * Vv + v) * Nn + n;
        }
    }
    const int ncol0 = NBase + warpN * 32 + (lane & 3) * 2;
#pragma unroll
    for (int mt = 0; mt < 4; mt++)
#pragma unroll
        for (int nt = 0; nt < 4; nt++) {
            __half2 h01 = __floats2half2_rn(acc[mt][nt][0], acc[mt][nt][1]);
            __half2 h23 = __floats2half2_rn(acc[mt][nt][2], acc[mt][nt][3]);
            *(__half2*)(Cout + (size_t)grow[mt * 2 + 0] * Cc + ncol0 + nt * 8) = h01;
            *(__half2*)(Cout + (size_t)grow[mt * 2 + 1] * Cc + ncol0 + nt * 8) = h23;
        }
}

// ---------------------------------------------------------------------------
// Flat GEMM for CW1 = c @ w1b. CTA 128x128, flat rows, 3-stage pipeline.
// ---------------------------------------------------------------------------
__global__ __launch_bounds__(256, 2)
void mma_gemm_flat(const __half* __restrict__ Aw, const __half* __restrict__ Bw,
                   __half* __restrict__ Cout) {
    extern __shared__ char smem[];
    const uint32_t sb = su32(smem);
    const int tid = threadIdx.x;
    const int lane = tid & 31;
    const int wid = tid >> 5;
    const int warpM = wid & 1;
    const int warpN = wid >> 1;
    const int MBase = blockIdx.y * 128;
    const int NBase = blockIdx.x * 128;

    const int lr = tid >> 1;
    const int lc = (tid & 1) * 64;
    const char* aRowPtr = (const char*)(Aw + (size_t)(MBase + lr) * Cc) + lc;
    const char* bRowPtr = (const char*)(Bw + (size_t)(NBase + lr) * Cc) + lc;
    uint32_t so[4];
#pragma unroll
    for (int j = 0; j < 4; j++)
        so[j] = (uint32_t)(lr * 128 + ((lc + j * 16) ^ ((lr & 7) << 4)));

    auto issue = [&](int chunk, int stg) {
        uint32_t base = sb + stg * STAGE_BYTES;
        const char* pa = aRowPtr + chunk * 128;
        const char* pb = bRowPtr + chunk * 128;
#pragma unroll
        for (int j = 0; j < 4; j++) {
            cpa16(base + so[j], pa + j * 16);
            cpa16(base + OFF_B + so[j], pb + j * 16);
        }
        cp_commit();
    };

    float acc[4][4][4];
#pragma unroll
    for (int mt = 0; mt < 4; mt++)
#pragma unroll
        for (int nt = 0; nt < 4; nt++)
#pragma unroll
            for (int e = 0; e < 4; e++) acc[mt][nt][e] = 0.f;

    const uint32_t swz = (uint32_t)((lane & 7) << 4);
    const uint32_t aRow0 = (uint32_t)(warpM * 64 + (lane & 15));
    const uint32_t nRow0 = (uint32_t)(warpN * 32 + (lane & 15));
    const uint32_t halfSel = (uint32_t)((lane >> 4) << 4);

    issue(0, 0);
    issue(1, 1);
#pragma unroll 1
    for (int i = 0; i < NCHUNK; i++) {
        if (i + 1 < NCHUNK) asm volatile("cp.async.wait_group 1;" ::: "memory");
        else                asm volatile("cp.async.wait_group 0;" ::: "memory");
        __syncthreads();
        if (i + 2 < NCHUNK) issue(i + 2, (i + 2) % NSTAGE);

        uint32_t base = sb + (i % NSTAGE) * STAGE_BYTES;
#pragma unroll
        for (int k16 = 0; k16 < 4; k16++) {
            const uint32_t bc = (uint32_t)(k16 * 32) + halfSel;
            uint32_t ah[4][4], bh[4][2];
#pragma unroll
            for (int mt = 0; mt < 4; mt++) {
                uint32_t ad = base + (aRow0 + mt * 16) * 128 + (bc ^ swz);
                ldsm4(ah[mt][0], ah[mt][1], ah[mt][2], ah[mt][3], ad);
            }
#pragma unroll
            for (int g = 0; g < 2; g++) {
                uint32_t ad = base + OFF_B + (nRow0 + g * 16) * 128 + (bc ^ swz);
                uint32_t r0, r1, r2, r3;
                ldsm4(r0, r1, r2, r3, ad);
                bh[g * 2 + 0][0] = r0; bh[g * 2 + 0][1] = r2;
                bh[g * 2 + 1][0] = r1; bh[g * 2 + 1][1] = r3;
            }
#pragma unroll
            for (int mt = 0; mt < 4; mt++)
#pragma unroll
                for (int nt = 0; nt < 4; nt++)
                    mma16816(acc[mt][nt], ah[mt], bh[nt]);
        }
    }

    const int ncol0 = NBase + warpN * 32 + (lane & 3) * 2;
#pragma unroll
    for (int mt = 0; mt < 4; mt++) {
        int m0 = MBase + warpM * 64 + mt * 16 + (lane >> 2);
#pragma unroll
        for (int nt = 0; nt < 4; nt++) {
            __half2 h01 = __floats2half2_rn(acc[mt][nt][0], acc[mt][nt][1]);
            __half2 h23 = __floats2half2_rn(acc[mt][nt][2], acc[mt][nt][3]);
            *(__half2*)(Cout + (size_t)m0 * Cc + ncol0 + nt * 8) = h01;
            *(__half2*)(Cout + (size_t)(m0 + 8) * Cc + ncol0 + nt * 8) = h23;
        }
    }
}

// ---------------------------------------------------------------------------
// Fused score + softmax + update, 8 bn-rows per block (784 blocks, 256 thr).
// Exact round-13 version (best measured): smem staging of CW1/b1/w2,
// tanh.approx.f16x2. Math unchanged — rel_err must stay 7.985e-4.
// ---------------------------------------------------------------------------
#define BN_PER_BLK 8
__global__ __launch_bounds__(256)
void score_update_kernel(const __half* __restrict__ XW1, const __half* __restrict__ CW1,
                         const float* __restrict__ b1, const float* __restrict__ w2,
                         const float* __restrict__ b2, const __half* __restrict__ P,
                         float* __restrict__ OutC, float* __restrict__ Rout, int last) {
    const int bn0 = blockIdx.x * BN_PER_BLK;
    const int tid = threadIdx.x;
    const int wid = tid >> 5;
    const int lane = tid & 31;

    __shared__ __half2 s_b1h[Hh / 2];                 // 1.5 KB
    __shared__ float   s_w2[Hh];                      // 3 KB
    __shared__ __half  s_cw[BN_PER_BLK * Hh];         // 12 KB (rows bn0..bn0+7)
    __shared__ float   s_a[BN_PER_BLK * Vv];

    // Phase 0: stage b1 (half2), w2 (fp32), 8 contiguous CW1 rows
    for (int j = tid; j < Hh / 2; j += 256) {
        float2 bv = *(const float2*)(b1 + 2 * j);
        s_b1h[j] = __floats2half2_rn(bv.x, bv.y);
    }
    for (int j = tid; j < Hh; j += 256) s_w2[j] = w2[j];
    {
        const uint4* src = (const uint4*)(CW1 + (size_t)bn0 * Hh);
        uint4* dst = (uint4*)s_cw;
#pragma unroll
        for (int j = 0; j < (BN_PER_BLK * Hh / 8) / 256; j++)   // 3 iters
            dst[tid + j * 256] = src[tid + j * 256];
    }
    __syncthreads();

    const float b2v = b2[0];

    // Phase 1: 40 dots, warp w handles d = w, w+8, ..., w+32
    float dots[5];
#pragma unroll
    for (int q = 0; q < 5; q++) {
        const int d = wid + q * 8;           // 0..39
        const int ln = d / Vv;               // local bn
        const int v  = d % Vv;
        const int bn = bn0 + ln;
        const int b = bn / Nn, n = bn % Nn;
        const __half* xr = XW1 + (size_t)((b * Vv + v) * Nn + n) * Hh;
        const __half* cw = s_cw + ln * Hh;
        float sum = 0.f;
#pragma unroll
        for (int h0 = lane * 8; h0 < Hh; h0 += 256) {
            uint4 xv = *(const uint4*)(xr + h0);
            uint4 cv = *(const uint4*)(cw + h0);
            const __half2* px = (const __half2*)&xv;
            const __half2* pc = (const __half2*)&cv;
#pragma unroll
            for (int j = 0; j < 4; j++) {
                __half2 arg = __hadd2(__hadd2(px[j], pc[j]), s_b1h[h0 / 2 + j]);
                uint32_t t2 = tanh2_fast(*(uint32_t*)&arg);
                float2 tf = __half22float2(*(__half2*)&t2);
                int h = h0 + 2 * j;
                sum = fmaf(tf.x, s_w2[h], sum);
                sum = fmaf(tf.y, s_w2[h + 1], sum);
            }
        }
#pragma unroll
        for (int off = 16; off; off >>= 1) sum += __shfl_xor_sync(0xFFFFFFFFu, sum, off);
        dots[q] = sum + b2v;
    }
    if (lane == 0) {
#pragma unroll
        for (int q = 0; q < 5; q++) s_a[wid + q * 8] = dots[q];
    }
    __syncthreads();

    // Phase 2: softmax per local bn (threads 0..7)
    if (tid < BN_PER_BLK) {
        float sv[Vv];
        float mx = -1e30f;
#pragma unroll
        for (int v = 0; v < Vv; v++) {
            sv[v] = s_a[tid * Vv + v];
            mx = fmaxf(mx, sv[v]);
        }
        float den = 0.f;
#pragma unroll
        for (int v = 0; v < Vv; v++) { sv[v] = __expf(sv[v] - mx); den += sv[v]; }
        float inv = 1.0f / den;
#pragma unroll
        for (int v = 0; v < Vv; v++) { sv[v] *= inv; s_a[tid * Vv + v] = sv[v]; }
        if (last) {
            float ent = 0.f;
#pragma unroll
            for (int v = 0; v < Vv; v++) ent -= sv[v] * __logf(sv[v] + 1e-8f);
            Rout[bn0 + tid] = 1.0f - ent * (1.0f / 1.6094379124341003f);  // 1/log(5)
        }
    }
    __syncthreads();

    // Phase 3: weighted sum. 8 ln x 192 chan-slots = 1536 slots / 256 thr = 6 its
#pragma unroll
    for (int it = 0; it < 6; it++) {
        const int slot = tid + it * 256;
        const int ln = slot / (Cc / 4);
        const int ch = (slot % (Cc / 4)) * 4;
        const int bn = bn0 + ln;
        const int b = bn / Nn, n = bn % Nn;
        float av[Vv];
#pragma unroll
        for (int v = 0; v < Vv; v++) av[v] = s_a[ln * Vv + v];
        float4 acc = make_float4(0.f, 0.f, 0.f, 0.f);
#pragma unroll
        for (int v = 0; v < Vv; v++) {
            uint2 pv = *(const uint2*)(P + ((size_t)((b * Vv + v) * Nn + n)) * Cc + ch);
            float2 p01 = __half22float2(*(__half2*)&pv.x);
            float2 p23 = __half22float2(*(__half2*)&pv.y);
            acc.x += av[v] * p01.x; acc.y += av[v] * p01.y;
            acc.z += av[v] * p23.x; acc.w += av[v] * p23.y;
        }
        if (last) {
            *(float4*)(OutC + (size_t)bn * Cc + ch) = acc;
        } else {
            __half2 a = __floats2half2_rn(acc.x, acc.y);
            __half2 bq = __floats2half2_rn(acc.z, acc.w);
            uint2 p;
            p.x = *(uint32_t*)&a;
            p.y = *(uint32_t*)&bq;
            *(uint2*)(g_ch + (size_t)bn * Cc + ch) = p;
        }
    }
}

// ---------------------------------------------------------------------------
// Launch
// ---------------------------------------------------------------------------
extern "C" void kernel_launch(void* const* d_in, const int* in_sizes, int n_in,
                              void* d_out, int out_size) {
    const float* x       = (const float*)d_in[0];
    const float* w_views = (const float*)d_in[1];
    const float* w1      = (const float*)d_in[2];
    const float* b1      = (const float*)d_in[3];
    const float* w2      = (const float*)d_in[4];
    const float* b2      = (const float*)d_in[5];
    float* out = (float*)d_out;   // c [B,N,C] then r [B,N]

    __half *P, *XW1, *CW1, *xh, *ch, *W;
    cudaGetSymbolAddress((void**)&P,   g_P);
    cudaGetSymbolAddress((void**)&XW1, g_XW1);
    cudaGetSymbolAddress((void**)&CW1, g_CW1);
    cudaGetSymbolAddress((void**)&xh,  g_xh);
    cudaGetSymbolAddress((void**)&ch,  g_ch);
    cudaGetSymbolAddress((void**)&W,   g_W);

    cudaFuncSetAttribute(mma_gemm_big,  cudaFuncAttributeMaxDynamicSharedMemorySize, SMEM_TOTAL);
    cudaFuncSetAttribute(mma_gemm_flat, cudaFuncAttributeMaxDynamicSharedMemorySize, SMEM_TOTAL);

    // conversions: one launch (weights + x/mean)
    prep_kernel<<<WBLKS + XBLKS, 256>>>(x, w_views, w1);

    // P = x @ w_views and XW1 = x @ w1[:C] in one launch
    {
        dim3 grid(12, BN_ROWS / 128, Vv);   // (12, 49, 5)
        mma_gemm_big<<<grid, 256, SMEM_TOTAL>>>(xh, W, P, XW1);
    }
    // iterations
    for (int it = 0; it < NUM_ITERS; it++) {
        dim3 gridc(Hh / 128, BN_ROWS / 128);   // (6, 49)
        mma_gemm_flat<<<gridc, 256, SMEM_TOTAL>>>(ch, W + (size_t)6 * WMAT, CW1);

        int last = (it == NUM_ITERS - 1) ? 1 : 0;
        float* rdst = out + (size_t)BN_ROWS * Cc;
        score_update_kernel<<<BN_ROWS / BN_PER_BLK, 256>>>(XW1, CW1, b1, w2, b2, P, out, rdst, last);
    }
    (void)in_sizes; (void)n_in; (void)out_size;
}

// round 16
// speedup vs baseline: 1.0798x; 1.0269x over previous
#include <cuda_runtime.h>
#include <cuda_fp16.h>
#include <cstdint>

#define Bb 32
#define Vv 5
#define Nn 196
#define Cc 768
#define Hh 768
#define BN_ROWS 6272            // Bb*Nn
#define BVN 31360               // Bb*Vv*Nn
#define NUM_ITERS 3
#define WMAT (Cc*Cc)            // 589824

// ---------------------------------------------------------------------------
// Scratch (device globals; no runtime allocation allowed) — all fp16
// ---------------------------------------------------------------------------
__device__ __half g_P[(size_t)BVN * Cc];        // proj_x
__device__ __half g_XW1[(size_t)BVN * Hh];      // x @ w1[:C]
__device__ __half g_CW1[(size_t)BN_ROWS * Hh];  // c @ w1[C:]
__device__ __half g_xh[(size_t)BVN * Cc];       // x (fp16)
__device__ __half g_ch[(size_t)BN_ROWS * Cc];   // c (fp16)
// 7 transposed [N,K] weight matrices (fp16): views 0..4, w1a=5, w1b=6
__device__ __half g_W[(size_t)7 * WMAT];

// ---------------------------------------------------------------------------
// Helpers
// ---------------------------------------------------------------------------
__device__ __forceinline__ uint32_t su32(const void* p) {
    uint32_t a;
    asm("{ .reg .u64 t; cvta.to.shared.u64 t, %1; cvt.u32.u64 %0, t; }" : "=r"(a) : "l"(p));
    return a;
}
__device__ __forceinline__ void cpa16(uint32_t d, const void* s) {
    asm volatile("cp.async.cg.shared.global [%0], [%1], 16;" :: "r"(d), "l"(s) : "memory");
}
__device__ __forceinline__ void cp_commit() {
    asm volatile("cp.async.commit_group;" ::: "memory");
}
__device__ __forceinline__ void ldsm4(uint32_t& r0, uint32_t& r1, uint32_t& r2, uint32_t& r3,
                                      uint32_t addr) {
    asm volatile("ldmatrix.sync.aligned.m8n8.x4.shared.b16 {%0,%1,%2,%3}, [%4];"
                 : "=r"(r0), "=r"(r1), "=r"(r2), "=r"(r3) : "r"(addr));
}
__device__ __forceinline__ void mma16816(float* d, const uint32_t* a, const uint32_t* b) {
    asm volatile(
        "mma.sync.aligned.m16n8k16.row.col.f32.f16.f16.f32 "
        "{%0,%1,%2,%3}, {%4,%5,%6,%7}, {%8,%9}, {%0,%1,%2,%3};"
        : "+f"(d[0]), "+f"(d[1]), "+f"(d[2]), "+f"(d[3])
        : "r"(a[0]), "r"(a[1]), "r"(a[2]), "r"(a[3]), "r"(b[0]), "r"(b[1]));
}
__device__ __forceinline__ uint32_t tanh2_fast(uint32_t x2) {
    uint32_t y;
    asm("tanh.approx.f16x2 %0, %1;" : "=r"(y) : "r"(x2));
    return y;
}

// ---------------------------------------------------------------------------
// Tiled, coalesced weight transpose: g_W[m][n][k] = src_m[k][n], fp16.
// grid (24, 24, 7), block (32, 8). smem 32x33 avoids bank conflicts.
// ---------------------------------------------------------------------------
__global__ void wtrans_kernel(const float* __restrict__ w_views,
                              const float* __restrict__ w1) {
    __shared__ float tile[32][33];
    const int m = blockIdx.z;
    const int k0 = blockIdx.y * 32;
    const int n0 = blockIdx.x * 32;
    const int tx = threadIdx.x, ty = threadIdx.y;

    const float* src;     // src[k][n], row length 768
    if (m < 5)      src = w_views + (size_t)m * WMAT;
    else if (m == 5) src = w1;
    else             src = w1 + (size_t)Cc * Hh;

#pragma unroll
    for (int j = 0; j < 4; j++) {
        int k = k0 + ty + j * 8;
        tile[ty + j * 8][tx] = src[(size_t)k * Hh + n0 + tx];
    }
    __syncthreads();
    __half* dst = g_W + (size_t)m * WMAT;
#pragma unroll
    for (int j = 0; j < 4; j++) {
        int n = n0 + ty + j * 8;
        dst[(size_t)n * Cc + k0 + tx] = __float2half_rn(tile[tx][ty + j * 8]);
    }
}

// ---------------------------------------------------------------------------
// x -> fp16 AND mean over views -> c0 (fp16). One pass over x.
// ---------------------------------------------------------------------------
__global__ void xmean_kernel(const float* __restrict__ x) {
    int i = blockIdx.x * blockDim.x + threadIdx.x;
    const int TOT = BN_ROWS * (Cc / 4);
    if (i >= TOT) return;
    int bn = i / (Cc / 4);
    int cq = (i % (Cc / 4)) * 4;
    int b = bn / Nn, n = bn % Nn;
    float4 acc = make_float4(0.f, 0.f, 0.f, 0.f);
#pragma unroll
    for (int v = 0; v < Vv; v++) {
        size_t row = (size_t)((b * Vv + v) * Nn + n);
        const float4 xv = *(const float4*)(x + row * Cc + cq);
        acc.x += xv.x; acc.y += xv.y; acc.z += xv.z; acc.w += xv.w;
        __half2 a = __floats2half2_rn(xv.x, xv.y);
        __half2 bq = __floats2half2_rn(xv.z, xv.w);
        uint2 p;
        p.x = *(uint32_t*)&a;
        p.y = *(uint32_t*)&bq;
        *(uint2*)(g_xh + row * Cc + cq) = p;
    }
    const float s = 1.0f / Vv;
    __half2 a = __floats2half2_rn(acc.x * s, acc.y * s);
    __half2 bq = __floats2half2_rn(acc.z * s, acc.w * s);
    uint2 p;
    p.x = *(uint32_t*)&a;
    p.y = *(uint32_t*)&bq;
    *(uint2*)(g_ch + (size_t)bn * Cc + cq) = p;
}

// ---------------------------------------------------------------------------
// GEMM core config: f32-accum HMMA, 3-stage cp.async, race-free sync->issue.
// ---------------------------------------------------------------------------
#define STAGE_BYTES 32768          // 2 tiles x 16KB (A, B)
#define NSTAGE 3
#define SMEM_TOTAL  (NSTAGE * STAGE_BYTES)
#define OFF_B  16384
#define NCHUNK 12

// ---------------------------------------------------------------------------
// Combined big GEMM: grid (12, 49, 5). v = blockIdx.z selects the per-view
// row gather. bx<6: B=W_v, out=P; bx>=6: B=w1a, out=XW1.
// ---------------------------------------------------------------------------
__global__ __launch_bounds__(256, 2)
void mma_gemm_big(const __half* __restrict__ Aw, const __half* __restrict__ Wall,
                  __half* __restrict__ P, __half* __restrict__ XW1) {
    extern __shared__ char smem[];
    const uint32_t sb = su32(smem);
    const int tid = threadIdx.x;
    const int lane = tid & 31;
    const int wid = tid >> 5;
    const int warpM = wid & 1;
    const int warpN = wid >> 1;
    const int v = blockIdx.z;
    const int bx = blockIdx.x;
    const bool isP = bx < 6;
    const int NBase = (isP ? bx : bx - 6) * 128;
    const int MBase = blockIdx.y * 128;
    const __half* Bw = Wall + (size_t)(isP ? v : 5) * WMAT;
    __half* Cout = isP ? P : XW1;

    const int lr = tid >> 1;
    const int lc = (tid & 1) * 64;
    int bn0 = MBase + lr;
    int b0 = bn0 / Nn, n0 = bn0 - b0 * Nn;
    int gaRow = (b0 * Vv + v) * Nn + n0;
    const char* aRowPtr = (const char*)(Aw + (size_t)gaRow * Cc) + lc;
    const char* bRowPtr = (const char*)(Bw + (size_t)(NBase + lr) * Cc) + lc;
    uint32_t so[4];
#pragma unroll
    for (int j = 0; j < 4; j++)
        so[j] = (uint32_t)(lr * 128 + ((lc + j * 16) ^ ((lr & 7) << 4)));

    auto issue = [&](int chunk, int stg) {
        uint32_t base = sb + stg * STAGE_BYTES;
        const char* pa = aRowPtr + chunk * 128;
        const char* pb = bRowPtr + chunk * 128;
#pragma unroll
        for (int j = 0; j < 4; j++) {
            cpa16(base + so[j], pa + j * 16);
            cpa16(base + OFF_B + so[j], pb + j * 16);
        }
        cp_commit();
    };

    float acc[4][4][4];
#pragma unroll
    for (int mt = 0; mt < 4; mt++)
#pragma unroll
        for (int nt = 0; nt < 4; nt++)
#pragma unroll
            for (int e = 0; e < 4; e++) acc[mt][nt][e] = 0.f;

    const uint32_t swz = (uint32_t)((lane & 7) << 4);
    const uint32_t aRow0 = (uint32_t)(warpM * 64 + (lane & 15));
    const uint32_t nRow0 = (uint32_t)(warpN * 32 + (lane & 15));
    const uint32_t halfSel = (uint32_t)((lane >> 4) << 4);

    issue(0, 0);
    issue(1, 1);
#pragma unroll 1
    for (int i = 0; i < NCHUNK; i++) {
        if (i + 1 < NCHUNK) asm volatile("cp.async.wait_group 1;" ::: "memory");
        else                asm volatile("cp.async.wait_group 0;" ::: "memory");
        __syncthreads();
        if (i + 2 < NCHUNK) issue(i + 2, (i + 2) % NSTAGE);

        uint32_t base = sb + (i % NSTAGE) * STAGE_BYTES;
#pragma unroll
        for (int k16 = 0; k16 < 4; k16++) {
            const uint32_t bc = (uint32_t)(k16 * 32) + halfSel;
            uint32_t ah[4][4], bh[4][2];
#pragma unroll
            for (int mt = 0; mt < 4; mt++) {
                uint32_t ad = base + (aRow0 + mt * 16) * 128 + (bc ^ swz);
                ldsm4(ah[mt][0], ah[mt][1], ah[mt][2], ah[mt][3], ad);
            }
#pragma unroll
            for (int g = 0; g < 2; g++) {
                uint32_t ad = base + OFF_B + (nRow0 + g * 16) * 128 + (bc ^ swz);
                uint32_t r0, r1, r2, r3;
                ldsm4(r0, r1, r2, r3, ad);
                bh[g * 2 + 0][0] = r0; bh[g * 2 + 0][1] = r2;
                bh[g * 2 + 1][0] = r1; bh[g * 2 + 1][1] = r3;
            }
#pragma unroll
            for (int mt = 0; mt < 4; mt++)
#pragma unroll
                for (int nt = 0; nt < 4; nt++)
                    mma16816(acc[mt][nt], ah[mt], bh[nt]);
        }
    }

    // ---- epilogue (fp16 stores, gathered rows) ----
    int grow[8];
#pragma unroll
    for (int mt = 0; mt < 4; mt++) {
#pragma unroll
        for (int h = 0; h < 2; h++) {
            int m = MBase + warpM * 64 + mt * 16 + (lane >> 2) + h * 8;
            int b = m / Nn, n = m - b * Nn;
            grow[mt * 2 + h] = (b * Vv + v) * Nn + n;
        }
    }
    const int ncol0 = NBase + warpN * 32 + (lane & 3) * 2;
#pragma unroll
    for (int mt = 0; mt < 4; mt++)
#pragma unroll
        for (int nt = 0; nt < 4; nt++) {
            __half2 h01 = __floats2half2_rn(acc[mt][nt][0], acc[mt][nt][1]);
            __half2 h23 = __floats2half2_rn(acc[mt][nt][2], acc[mt][nt][3]);
            *(__half2*)(Cout + (size_t)grow[mt * 2 + 0] * Cc + ncol0 + nt * 8) = h01;
            *(__half2*)(Cout + (size_t)grow[mt * 2 + 1] * Cc + ncol0 + nt * 8) = h23;
        }
}

// ---------------------------------------------------------------------------
// Flat GEMM for CW1 = c @ w1b. CTA 128x128, flat rows, 3-stage pipeline.
// ---------------------------------------------------------------------------
__global__ __launch_bounds__(256, 2)
void mma_gemm_flat(const __half* __restrict__ Aw, const __half* __restrict__ Bw,
                   __half* __restrict__ Cout) {
    extern __shared__ char smem[];
    const uint32_t sb = su32(smem);
    const int tid = threadIdx.x;
    const int lane = tid & 31;
    const int wid = tid >> 5;
    const int warpM = wid & 1;
    const int warpN = wid >> 1;
    const int MBase = blockIdx.y * 128;
    const int NBase = blockIdx.x * 128;

    const int lr = tid >> 1;
    const int lc = (tid & 1) * 64;
    const char* aRowPtr = (const char*)(Aw + (size_t)(MBase + lr) * Cc) + lc;
    const char* bRowPtr = (const char*)(Bw + (size_t)(NBase + lr) * Cc) + lc;
    uint32_t so[4];
#pragma unroll
    for (int j = 0; j < 4; j++)
        so[j] = (uint32_t)(lr * 128 + ((lc + j * 16) ^ ((lr & 7) << 4)));

    auto issue = [&](int chunk, int stg) {
        uint32_t base = sb + stg * STAGE_BYTES;
        const char* pa = aRowPtr + chunk * 128;
        const char* pb = bRowPtr + chunk * 128;
#pragma unroll
        for (int j = 0; j < 4; j++) {
            cpa16(base + so[j], pa + j * 16);
            cpa16(base + OFF_B + so[j], pb + j * 16);
        }
        cp_commit();
    };

    float acc[4][4][4];
#pragma unroll
    for (int mt = 0; mt < 4; mt++)
#pragma unroll
        for (int nt = 0; nt < 4; nt++)
#pragma unroll
            for (int e = 0; e < 4; e++) acc[mt][nt][e] = 0.f;

    const uint32_t swz = (uint32_t)((lane & 7) << 4);
    const uint32_t aRow0 = (uint32_t)(warpM * 64 + (lane & 15));
    const uint32_t nRow0 = (uint32_t)(warpN * 32 + (lane & 15));
    const uint32_t halfSel = (uint32_t)((lane >> 4) << 4);

    issue(0, 0);
    issue(1, 1);
#pragma unroll 1
    for (int i = 0; i < NCHUNK; i++) {
        if (i + 1 < NCHUNK) asm volatile("cp.async.wait_group 1;" ::: "memory");
        else                asm volatile("cp.async.wait_group 0;" ::: "memory");
        __syncthreads();
        if (i + 2 < NCHUNK) issue(i + 2, (i + 2) % NSTAGE);

        uint32_t base = sb + (i % NSTAGE) * STAGE_BYTES;
#pragma unroll
        for (int k16 = 0; k16 < 4; k16++) {
            const uint32_t bc = (uint32_t)(k16 * 32) + halfSel;
            uint32_t ah[4][4], bh[4][2];
#pragma unroll
            for (int mt = 0; mt < 4; mt++) {
                uint32_t ad = base + (aRow0 + mt * 16) * 128 + (bc ^ swz);
                ldsm4(ah[mt][0], ah[mt][1], ah[mt][2], ah[mt][3], ad);
            }
#pragma unroll
            for (int g = 0; g < 2; g++) {
                uint32_t ad = base + OFF_B + (nRow0 + g * 16) * 128 + (bc ^ swz);
                uint32_t r0, r1, r2, r3;
                ldsm4(r0, r1, r2, r3, ad);
                bh[g * 2 + 0][0] = r0; bh[g * 2 + 0][1] = r2;
                bh[g * 2 + 1][0] = r1; bh[g * 2 + 1][1] = r3;
            }
#pragma unroll
            for (int mt = 0; mt < 4; mt++)
#pragma unroll
                for (int nt = 0; nt < 4; nt++)
                    mma16816(acc[mt][nt], ah[mt], bh[nt]);
        }
    }

    const int ncol0 = NBase + warpN * 32 + (lane & 3) * 2;
#pragma unroll
    for (int mt = 0; mt < 4; mt++) {
        int m0 = MBase + warpM * 64 + mt * 16 + (lane >> 2);
#pragma unroll
        for (int nt = 0; nt < 4; nt++) {
            __half2 h01 = __floats2half2_rn(acc[mt][nt][0], acc[mt][nt][1]);
            __half2 h23 = __floats2half2_rn(acc[mt][nt][2], acc[mt][nt][3]);
            *(__half2*)(Cout + (size_t)m0 * Cc + ncol0 + nt * 8) = h01;
            *(__half2*)(Cout + (size_t)(m0 + 8) * Cc + ncol0 + nt * 8) = h23;
        }
    }
}

// ---------------------------------------------------------------------------
// Fused score + softmax + update, 8 bn-rows per block (784 blocks, 256 thr).
// Exact R13/R15 math. __launch_bounds__(256,3) raises occupancy for latency.
// ---------------------------------------------------------------------------
#define BN_PER_BLK 8
__global__ __launch_bounds__(256, 3)
void score_update_kernel(const __half* __restrict__ XW1, const __half* __restrict__ CW1,
                         const float* __restrict__ b1, const float* __restrict__ w2,
                         const float* __restrict__ b2, const __half* __restrict__ P,
                         float* __restrict__ OutC, float* __restrict__ Rout, int last) {
    const int bn0 = blockIdx.x * BN_PER_BLK;
    const int tid = threadIdx.x;
    const int wid = tid >> 5;
    const int lane = tid & 31;

    __shared__ __half2 s_b1h[Hh / 2];                 // 1.5 KB
    __shared__ float   s_w2[Hh];                      // 3 KB
    __shared__ __half  s_cw[BN_PER_BLK * Hh];         // 12 KB (rows bn0..bn0+7)
    __shared__ float   s_a[BN_PER_BLK * Vv];

    // Phase 0: stage b1 (half2), w2 (fp32), 8 contiguous CW1 rows
    for (int j = tid; j < Hh / 2; j += 256) {
        float2 bv = *(const float2*)(b1 + 2 * j);
        s_b1h[j] = __floats2half2_rn(bv.x, bv.y);
    }
    for (int j = tid; j < Hh; j += 256) s_w2[j] = w2[j];
    {
        const uint4* src = (const uint4*)(CW1 + (size_t)bn0 * Hh);
        uint4* dst = (uint4*)s_cw;
#pragma unroll
        for (int j = 0; j < (BN_PER_BLK * Hh / 8) / 256; j++)   // 3 iters
            dst[tid + j * 256] = src[tid + j * 256];
    }
    __syncthreads();

    const float b2v = b2[0];

    // Phase 1: 40 dots, warp w handles d = w, w+8, ..., w+32
    float dots[5];
#pragma unroll
    for (int q = 0; q < 5; q++) {
        const int d = wid + q * 8;           // 0..39
        const int ln = d / Vv;               // local bn
        const int v  = d % Vv;
        const int bn = bn0 + ln;
        const int b = bn / Nn, n = bn % Nn;
        const __half* xr = XW1 + (size_t)((b * Vv + v) * Nn + n) * Hh;
        const __half* cw = s_cw + ln * Hh;
        float sum = 0.f;
#pragma unroll
        for (int h0 = lane * 8; h0 < Hh; h0 += 256) {
            uint4 xv = *(const uint4*)(xr + h0);
            uint4 cv = *(const uint4*)(cw + h0);
            const __half2* px = (const __half2*)&xv;
            const __half2* pc = (const __half2*)&cv;
#pragma unroll
            for (int j = 0; j < 4; j++) {
                __half2 arg = __hadd2(__hadd2(px[j], pc[j]), s_b1h[h0 / 2 + j]);
                uint32_t t2 = tanh2_fast(*(uint32_t*)&arg);
                float2 tf = __half22float2(*(__half2*)&t2);
                int h = h0 + 2 * j;
                sum = fmaf(tf.x, s_w2[h], sum);
                sum = fmaf(tf.y, s_w2[h + 1], sum);
            }
        }
#pragma unroll
        for (int off = 16; off; off >>= 1) sum += __shfl_xor_sync(0xFFFFFFFFu, sum, off);
        dots[q] = sum + b2v;
    }
    if (lane == 0) {
#pragma unroll
        for (int q = 0; q < 5; q++) s_a[wid + q * 8] = dots[q];
    }
    __syncthreads();

    // Phase 2: softmax per local bn (threads 0..7)
    if (tid < BN_PER_BLK) {
        float sv[Vv];
        float mx = -1e30f;
#pragma unroll
        for (int v = 0; v < Vv; v++) {
            sv[v] = s_a[tid * Vv + v];
            mx = fmaxf(mx, sv[v]);
        }
        float den = 0.f;
#pragma unroll
        for (int v = 0; v < Vv; v++) { sv[v] = __expf(sv[v] - mx); den += sv[v]; }
        float inv = 1.0f / den;
#pragma unroll
        for (int v = 0; v < Vv; v++) { sv[v] *= inv; s_a[tid * Vv + v] = sv[v]; }
        if (last) {
            float ent = 0.f;
#pragma unroll
            for (int v = 0; v < Vv; v++) ent -= sv[v] * __logf(sv[v] + 1e-8f);
            Rout[bn0 + tid] = 1.0f - ent * (1.0f / 1.6094379124341003f);  // 1/log(5)
        }
    }
    __syncthreads();

    // Phase 3: weighted sum. 8 ln x 192 chan-slots = 1536 slots / 256 thr = 6 its
#pragma unroll
    for (int it = 0; it < 6; it++) {
        const int slot = tid + it * 256;
        const int ln = slot / (Cc / 4);
        const int ch = (slot % (Cc / 4)) * 4;
        const int bn = bn0 + ln;
        const int b = bn / Nn, n = bn % Nn;
        float av[Vv];
#pragma unroll
        for (int v = 0; v < Vv; v++) av[v] = s_a[ln * Vv + v];
        float4 acc = make_float4(0.f, 0.f, 0.f, 0.f);
#pragma unroll
        for (int v = 0; v < Vv; v++) {
            uint2 pv = *(const uint2*)(P + ((size_t)((b * Vv + v) * Nn + n)) * Cc + ch);
            float2 p01 = __half22float2(*(__half2*)&pv.x);
            float2 p23 = __half22float2(*(__half2*)&pv.y);
            acc.x += av[v] * p01.x; acc.y += av[v] * p01.y;
            acc.z += av[v] * p23.x; acc.w += av[v] * p23.y;
        }
        if (last) {
            *(float4*)(OutC + (size_t)bn * Cc + ch) = acc;
        } else {
            __half2 a = __floats2half2_rn(acc.x, acc.y);
            __half2 bq = __floats2half2_rn(acc.z, acc.w);
            uint2 p;
            p.x = *(uint32_t*)&a;
            p.y = *(uint32_t*)&bq;
            *(uint2*)(g_ch + (size_t)bn * Cc + ch) = p;
        }
    }
}

// ---------------------------------------------------------------------------
// Launch
// ---------------------------------------------------------------------------
extern "C" void kernel_launch(void* const* d_in, const int* in_sizes, int n_in,
                              void* d_out, int out_size) {
    const float* x       = (const float*)d_in[0];
    const float* w_views = (const float*)d_in[1];
    const float* w1      = (const float*)d_in[2];
    const float* b1      = (const float*)d_in[3];
    const float* w2      = (const float*)d_in[4];
    const float* b2      = (const float*)d_in[5];
    float* out = (float*)d_out;   // c [B,N,C] then r [B,N]

    __half *P, *XW1, *CW1, *xh, *ch, *W;
    cudaGetSymbolAddress((void**)&P,   g_P);
    cudaGetSymbolAddress((void**)&XW1, g_XW1);
    cudaGetSymbolAddress((void**)&CW1, g_CW1);
    cudaGetSymbolAddress((void**)&xh,  g_xh);
    cudaGetSymbolAddress((void**)&ch,  g_ch);
    cudaGetSymbolAddress((void**)&W,   g_W);

    cudaFuncSetAttribute(mma_gemm_big,  cudaFuncAttributeMaxDynamicSharedMemorySize, SMEM_TOTAL);
    cudaFuncSetAttribute(mma_gemm_flat, cudaFuncAttributeMaxDynamicSharedMemorySize, SMEM_TOTAL);

    // conversions: tiled coalesced weight transpose + x/mean pass
    {
        dim3 wgrid(Cc / 32, Cc / 32, 7);    // (24, 24, 7)
        wtrans_kernel<<<wgrid, dim3(32, 8)>>>(w_views, w1);
        int tm = BN_ROWS * (Cc / 4);
        xmean_kernel<<<(tm + 255) / 256, 256>>>(x);
    }
    // P = x @ w_views and XW1 = x @ w1[:C] in one launch
    {
        dim3 grid(12, BN_ROWS / 128, Vv);   // (12, 49, 5)
        mma_gemm_big<<<grid, 256, SMEM_TOTAL>>>(xh, W, P, XW1);
    }
    // iterations
    for (int it = 0; it < NUM_ITERS; it++) {
        dim3 gridc(Hh / 128, BN_ROWS / 128);   // (6, 49)
        mma_gemm_flat<<<gridc, 256, SMEM_TOTAL>>>(ch, W + (size_t)6 * WMAT, CW1);

        int last = (it == NUM_ITERS - 1) ? 1 : 0;
        float* rdst = out + (size_t)BN_ROWS * Cc;
        score_update_kernel<<<BN_ROWS / BN_PER_BLK, 256>>>(XW1, CW1, b1, w2, b2, P, out, rdst, last);
    }
    (void)in_sizes; (void)n_in; (void)out_size;
}